// round 1
// baseline (speedup 1.0000x reference)
#include <cuda_runtime.h>
#include <mma.h>
#include <math.h>

namespace wm = nvcuda::wmma;

#define HID    256
#define NHALF  128
#define MAXA   400000
#define MAXT   100000

// ---------------- scratch (device globals: no allocation allowed) ----------
__device__ float g_exp[MAXA];                 // exp(score) per agent
__device__ float g_denom[MAXT];
__device__ int   g_count[MAXT];
__device__ int   g_offs[MAXT];
__device__ int   g_cursor[MAXT];
__device__ int   g_list[MAXA];
__device__ int   g_bsum[256];
__device__ int   g_idxflag;                   // 1 = team_idx is int64, 0 = int32
__device__ float g_teamh[25600000];           // 100000 x 256 pooled (pre-projection)

__device__ __forceinline__ int team_of(const void* ti, int a, int f64) {
    return f64 ? (int)((const long long*)ti)[a] : ((const int*)ti)[a];
}

// ---------------- dtype detection for team_idx ------------------------------
__global__ void k_detect(const void* __restrict__ ti, int nA, int nT) {
    if (blockIdx.x == 0 && threadIdx.x == 0) {
        const long long* p = (const long long*)ti;
        int n = nA < 64 ? nA : 64;
        int ok64 = 1;
        for (int i = 0; i < n; i++) {
            long long v = p[i];
            if (v < 0 || v >= (long long)nT) { ok64 = 0; break; }
        }
        g_idxflag = ok64;
    }
}

// ---------------- GEMM1: scores -> exp(score) -------------------------------
// C = tanh(A[nA,256] @ W1[256,128] + b1) @ W2[128] + b2 ; g_exp = exp(C)
// block: 256 thr (8 warps, 4x2), tile M=64, N=128(full), K=256(full in smem)
#define W1_LD 132
#define AS_LD 264
#define HS_LD 132
#define SMEM_BYTES ((256*W1_LD + 64*AS_LD + 128 + 128) * 4)

__global__ void k_gemm1(const float* __restrict__ A, const float* __restrict__ W1,
                        const float* __restrict__ b1, const float* __restrict__ W2,
                        const float* __restrict__ b2p, int nA)
{
    extern __shared__ float sm[];
    float* W1s = sm;                       // 256 x 132
    float* As  = sm + 256 * W1_LD;         // 64 x 264 (also reused as Hs 64x132)
    float* b1s = As + 64 * AS_LD;          // 128
    float* W2s = b1s + 128;                // 128

    const int tid = threadIdx.x;
    // stage W1 (tf32-converted) once
    for (int i = tid; i < 256 * 128 / 4; i += 256) {
        int r = i >> 5, c4 = i & 31;
        float4 v = ((const float4*)W1)[i];
        float* d = &W1s[r * W1_LD + c4 * 4];
        d[0] = wm::__float_to_tf32(v.x); d[1] = wm::__float_to_tf32(v.y);
        d[2] = wm::__float_to_tf32(v.z); d[3] = wm::__float_to_tf32(v.w);
    }
    if (tid < 128) { b1s[tid] = b1[tid]; W2s[tid] = W2[tid]; }
    const float b2 = b2p[0];

    const int warp = tid >> 5, lane = tid & 31;
    const int wmrow = warp >> 1, wncol = warp & 1;
    const int ntiles = (nA + 63) >> 6;

    for (int tile = blockIdx.x; tile < ntiles; tile += gridDim.x) {
        const int row0 = tile << 6;
        __syncthreads();   // previous epilogue done reading Hs(=As)
        // stage A tile 64x256 (tf32)
        for (int i = tid; i < 4096; i += 256) {
            int r = i >> 6, c4 = i & 63;
            int g = row0 + r;
            float4 v = (g < nA) ? ((const float4*)A)[(size_t)g * 64 + c4]
                                : make_float4(0.f, 0.f, 0.f, 0.f);
            float* d = &As[r * AS_LD + c4 * 4];
            d[0] = wm::__float_to_tf32(v.x); d[1] = wm::__float_to_tf32(v.y);
            d[2] = wm::__float_to_tf32(v.z); d[3] = wm::__float_to_tf32(v.w);
        }
        __syncthreads();

        wm::fragment<wm::accumulator, 16, 16, 8, float> acc[4];
        #pragma unroll
        for (int j = 0; j < 4; j++) wm::fill_fragment(acc[j], 0.0f);

        #pragma unroll 4
        for (int k = 0; k < 256; k += 8) {
            wm::fragment<wm::matrix_a, 16, 16, 8, wm::precision::tf32, wm::row_major> af;
            wm::load_matrix_sync(af, &As[(wmrow * 16) * AS_LD + k], AS_LD);
            #pragma unroll
            for (int j = 0; j < 4; j++) {
                wm::fragment<wm::matrix_b, 16, 16, 8, wm::precision::tf32, wm::row_major> bf;
                wm::load_matrix_sync(bf, &W1s[k * W1_LD + wncol * 64 + j * 16], W1_LD);
                wm::mma_sync(acc[j], af, bf, acc[j]);
            }
        }
        __syncthreads();   // all warps done reading As before overwriting as Hs
        float* Hs = As;    // 64 x HS_LD
        #pragma unroll
        for (int j = 0; j < 4; j++)
            wm::store_matrix_sync(&Hs[(wmrow * 16) * HS_LD + wncol * 64 + j * 16],
                                  acc[j], HS_LD, wm::mem_row_major);
        __syncthreads();

        // epilogue: per row tanh, dot with W2, exp
        #pragma unroll
        for (int r8 = 0; r8 < 8; r8++) {
            int r = warp * 8 + r8;
            int g = row0 + r;
            const float4 h = *(const float4*)&Hs[r * HS_LD + lane * 4];
            int c = lane * 4;
            float s = tanhf(h.x + b1s[c])     * W2s[c]
                    + tanhf(h.y + b1s[c + 1]) * W2s[c + 1]
                    + tanhf(h.z + b1s[c + 2]) * W2s[c + 2]
                    + tanhf(h.w + b1s[c + 3]) * W2s[c + 3];
            #pragma unroll
            for (int o = 16; o > 0; o >>= 1) s += __shfl_xor_sync(0xffffffffu, s, o);
            if (lane == 0 && g < nA) g_exp[g] = expf(s + b2);
        }
    }
}

// ---------------- small helpers: clear / denom / scan / scatter -------------
__global__ void k_clear(int nT) {
    int i = blockIdx.x * blockDim.x + threadIdx.x;
    if (i < nT) { g_denom[i] = 0.f; g_count[i] = 0; g_cursor[i] = 0; }
}

__global__ void k_accum(const void* __restrict__ ti, int nA) {
    int a = blockIdx.x * blockDim.x + threadIdx.x;
    if (a >= nA) return;
    int t = team_of(ti, a, g_idxflag);
    atomicAdd(&g_denom[t], g_exp[a]);
    atomicAdd(&g_count[t], 1);
}

__global__ void k_scan1(int nT) {
    __shared__ int ws[32];
    int i = blockIdx.x * 1024 + threadIdx.x;
    int lane = threadIdx.x & 31, wid = threadIdx.x >> 5;
    int v = (i < nT) ? g_count[i] : 0;
    int inc = v;
    #pragma unroll
    for (int o = 1; o < 32; o <<= 1) {
        int n = __shfl_up_sync(0xffffffffu, inc, o);
        if (lane >= o) inc += n;
    }
    if (lane == 31) ws[wid] = inc;
    __syncthreads();
    if (wid == 0) {
        int t = ws[lane];
        #pragma unroll
        for (int o = 1; o < 32; o <<= 1) {
            int n = __shfl_up_sync(0xffffffffu, t, o);
            if (lane >= o) t += n;
        }
        ws[lane] = t;
    }
    __syncthreads();
    int warpPre = wid ? ws[wid - 1] : 0;
    if (i < nT) g_offs[i] = warpPre + inc - v;
    if (threadIdx.x == 1023) g_bsum[blockIdx.x] = warpPre + inc;
}

__global__ void k_scan2(int nb) {
    if (threadIdx.x == 0 && blockIdx.x == 0) {
        int run = 0;
        for (int b = 0; b < nb; b++) { int t = g_bsum[b]; g_bsum[b] = run; run += t; }
    }
}

__global__ void k_scan3(int nT) {
    int i = blockIdx.x * blockDim.x + threadIdx.x;
    if (i < nT) g_offs[i] += g_bsum[i >> 10];
}

__global__ void k_scatter(const void* __restrict__ ti, int nA) {
    int a = blockIdx.x * blockDim.x + threadIdx.x;
    if (a >= nA) return;
    int t = team_of(ti, a, g_idxflag);
    int p = atomicAdd(&g_cursor[t], 1);
    g_list[g_offs[t] + p] = a;
}

// ---------------- pool: warp per team ---------------------------------------
__global__ void k_pool(const float* __restrict__ A, float* __restrict__ attn, int nT) {
    int t = (blockIdx.x * blockDim.x + threadIdx.x) >> 5;
    if (t >= nT) return;
    int lane = threadIdx.x & 31;
    int start = g_offs[t];
    int cnt   = g_count[t];
    float inv = (cnt > 0) ? (1.0f / g_denom[t]) : 0.0f;
    float4 a0 = make_float4(0.f, 0.f, 0.f, 0.f);
    float4 a1 = make_float4(0.f, 0.f, 0.f, 0.f);
    for (int i = 0; i < cnt; i++) {
        int a = g_list[start + i];
        float w = g_exp[a] * inv;
        const float4* row = (const float4*)A + (size_t)a * 64;
        float4 v0 = row[lane * 2], v1 = row[lane * 2 + 1];
        a0.x += w * v0.x; a0.y += w * v0.y; a0.z += w * v0.z; a0.w += w * v0.w;
        a1.x += w * v1.x; a1.y += w * v1.y; a1.z += w * v1.z; a1.w += w * v1.w;
        if (lane == 0) attn[a] = w;
    }
    float4* dst = (float4*)g_teamh + (size_t)t * 64;
    dst[lane * 2] = a0; dst[lane * 2 + 1] = a1;
}

// ---------------- GEMM3: out = relu(team_h @ Wo + bo) -----------------------
// two "colors": each block owns 128 output columns (Wo half resident in smem)
__global__ void k_gemm3(const float* __restrict__ Wo, const float* __restrict__ bo,
                        float* __restrict__ out, int nT)
{
    extern __shared__ float sm[];
    float* Ws  = sm;                       // 256 x 132
    float* Ts  = sm + 256 * W1_LD;         // 64 x 264 (reused as Cs 64x132)
    float* bos = Ts + 64 * AS_LD;          // 128

    const int tid = threadIdx.x;
    const int color = blockIdx.x & 1;
    const int nOff = color * 128;

    for (int i = tid; i < 256 * 128 / 4; i += 256) {
        int r = i >> 5, c4 = i & 31;
        float4 v = ((const float4*)Wo)[r * 64 + (nOff >> 2) + c4];
        float* d = &Ws[r * W1_LD + c4 * 4];
        d[0] = wm::__float_to_tf32(v.x); d[1] = wm::__float_to_tf32(v.y);
        d[2] = wm::__float_to_tf32(v.z); d[3] = wm::__float_to_tf32(v.w);
    }
    if (tid < 128) bos[tid] = bo[nOff + tid];

    const int warp = tid >> 5, lane = tid & 31;
    const int wmrow = warp >> 1, wncol = warp & 1;
    const int ntiles = (nT + 63) >> 6;
    const int tstride = gridDim.x >> 1;

    for (int tile = blockIdx.x >> 1; tile < ntiles; tile += tstride) {
        const int row0 = tile << 6;
        __syncthreads();
        for (int i = tid; i < 4096; i += 256) {
            int r = i >> 6, c4 = i & 63;
            int g = row0 + r;
            float4 v = (g < nT) ? ((const float4*)g_teamh)[(size_t)g * 64 + c4]
                                : make_float4(0.f, 0.f, 0.f, 0.f);
            float* d = &Ts[r * AS_LD + c4 * 4];
            d[0] = wm::__float_to_tf32(v.x); d[1] = wm::__float_to_tf32(v.y);
            d[2] = wm::__float_to_tf32(v.z); d[3] = wm::__float_to_tf32(v.w);
        }
        __syncthreads();

        wm::fragment<wm::accumulator, 16, 16, 8, float> acc[4];
        #pragma unroll
        for (int j = 0; j < 4; j++) wm::fill_fragment(acc[j], 0.0f);

        #pragma unroll 4
        for (int k = 0; k < 256; k += 8) {
            wm::fragment<wm::matrix_a, 16, 16, 8, wm::precision::tf32, wm::row_major> af;
            wm::load_matrix_sync(af, &Ts[(wmrow * 16) * AS_LD + k], AS_LD);
            #pragma unroll
            for (int j = 0; j < 4; j++) {
                wm::fragment<wm::matrix_b, 16, 16, 8, wm::precision::tf32, wm::row_major> bf;
                wm::load_matrix_sync(bf, &Ws[k * W1_LD + wncol * 64 + j * 16], W1_LD);
                wm::mma_sync(acc[j], af, bf, acc[j]);
            }
        }
        __syncthreads();
        float* Cs = Ts;
        #pragma unroll
        for (int j = 0; j < 4; j++)
            wm::store_matrix_sync(&Cs[(wmrow * 16) * HS_LD + wncol * 64 + j * 16],
                                  acc[j], HS_LD, wm::mem_row_major);
        __syncthreads();

        #pragma unroll
        for (int r8 = 0; r8 < 8; r8++) {
            int r = warp * 8 + r8;
            int g = row0 + r;
            if (g >= nT) continue;
            int c = lane * 4;
            float4 h = *(const float4*)&Cs[r * HS_LD + c];
            h.x = fmaxf(h.x + bos[c],     0.f);
            h.y = fmaxf(h.y + bos[c + 1], 0.f);
            h.z = fmaxf(h.z + bos[c + 2], 0.f);
            h.w = fmaxf(h.w + bos[c + 3], 0.f);
            *(float4*)&out[(size_t)g * 256 + nOff + c] = h;
        }
    }
}

// ---------------- launch -----------------------------------------------------
extern "C" void kernel_launch(void* const* d_in, const int* in_sizes, int n_in,
                              void* d_out, int out_size)
{
    const float* agent_h  = (const float*)d_in[0];
    const void*  team_idx = d_in[1];
    // n_teams scalar may or may not occupy slot 2
    int wbase = (in_sizes[2] == 256 * 128) ? 2 : 3;
    const float* W1 = (const float*)d_in[wbase + 0];
    const float* b1 = (const float*)d_in[wbase + 1];
    const float* W2 = (const float*)d_in[wbase + 2];
    const float* b2 = (const float*)d_in[wbase + 3];
    const float* Wo = (const float*)d_in[wbase + 4];
    const float* bo = (const float*)d_in[wbase + 5];

    const int nA = in_sizes[0] / 256;
    const int nT = (out_size - nA) / 256;
    float* out  = (float*)d_out;
    float* attn = out + (size_t)nT * 256;

    cudaFuncSetAttribute(k_gemm1, cudaFuncAttributeMaxDynamicSharedMemorySize, SMEM_BYTES);
    cudaFuncSetAttribute(k_gemm3, cudaFuncAttributeMaxDynamicSharedMemorySize, SMEM_BYTES);

    const int nb = (nT + 1023) / 1024;

    k_detect<<<1, 32>>>(team_idx, nA, nT);
    k_gemm1<<<152, 256, SMEM_BYTES>>>(agent_h, W1, b1, W2, b2, nA);
    k_clear<<<(nT + 255) / 256, 256>>>(nT);
    k_accum<<<(nA + 255) / 256, 256>>>(team_idx, nA);
    k_scan1<<<nb, 1024>>>(nT);
    k_scan2<<<1, 32>>>(nb);
    k_scan3<<<(nT + 255) / 256, 256>>>(nT);
    k_scatter<<<(nA + 255) / 256, 256>>>(team_idx, nA);
    k_pool<<<(nT + 7) / 8, 256>>>(agent_h, attn, nT);
    k_gemm3<<<304, 256, SMEM_BYTES>>>(Wo, bo, out, nT);
}

// round 2
// speedup vs baseline: 1.4399x; 1.4399x over previous
#include <cuda_runtime.h>
#include <mma.h>

namespace wm = nvcuda::wmma;

#define MAXA 400000
#define MAXT 100000

// ---------------- device scratch ---------------------------------------------
__device__ float g_exp[MAXA];
__device__ float g_denom[MAXT];
__device__ int   g_count[MAXT];
__device__ int   g_offs[MAXT];
__device__ int   g_cursor[MAXT];
__device__ int2  g_pair[MAXA];          // (agent, weight bits) sorted by team
__device__ int   g_bsum[256];
__device__ int   g_idxflag;             // 1 = int64 team_idx, 0 = int32
__device__ float g_teamh[MAXT * 256];

__device__ __forceinline__ int team_of(const void* ti, int a, int f64) {
    return f64 ? (int)((const long long*)ti)[a] : ((const int*)ti)[a];
}
__device__ __forceinline__ float fast_tanh(float x) {
    float y; asm("tanh.approx.f32 %0, %1;" : "=f"(y) : "f"(x)); return y;
}
__device__ __forceinline__ float fast_exp(float x) {
    float y; asm("ex2.approx.f32 %0, %1;" : "=f"(y) : "f"(x * 1.4426950408889634f));
    return y;
}

// smem: As = 2 x (64 x 264) float buffers (aliased as W 256x132 during preload)
//       Hs = 64 x 132, then 2 x 128 for biases
#define SM_FLOATS (33792 + 8448 + 256)
#define SM_BYTES  (SM_FLOATS * 4)

// ---------------- init: clear team arrays + detect idx dtype ----------------
__global__ void k_init(const void* __restrict__ ti, int nA, int nT) {
    int i = blockIdx.x * blockDim.x + threadIdx.x;
    if (i < nT) { g_denom[i] = 0.f; g_count[i] = 0; g_cursor[i] = 0; }
    if (blockIdx.x == 0 && threadIdx.x < 32) {
        const long long* p = (const long long*)ti;
        int n = nA < 64 ? nA : 64;
        bool bad = false;
        for (int j = threadIdx.x; j < n; j += 32) {
            long long v = p[j];
            if (v < 0 || v >= (long long)nT) bad = true;
        }
        unsigned m = __ballot_sync(0xffffffffu, bad);
        if (threadIdx.x == 0) g_idxflag = (m == 0) ? 1 : 0;
    }
}

// ---------------- GEMM1: g_exp = exp(tanh(A@W1+b1)@W2 + b2) -----------------
__global__ void __launch_bounds__(256, 1)
k_gemm1(const float* __restrict__ A, const float* __restrict__ W1,
        const float* __restrict__ b1, const float* __restrict__ W2,
        const float* __restrict__ b2p, int nA)
{
    extern __shared__ float sm[];
    float* As  = sm;                 // 2 x 16896
    float* Hs  = sm + 33792;         // 64 x 132
    float* b1s = Hs + 8448;
    float* W2s = b1s + 128;
    const int tid = threadIdx.x, warp = tid >> 5, lane = tid & 31;

    // stage W1 (RN tf32) into the A-buffer region, preload B fragments to regs
    for (int i = tid; i < 8192; i += 256) {
        int r = i >> 5, c4 = i & 31;
        float4 v = ((const float4*)W1)[i];
        float* d = &sm[r * 132 + c4 * 4];
        d[0] = wm::__float_to_tf32(v.x); d[1] = wm::__float_to_tf32(v.y);
        d[2] = wm::__float_to_tf32(v.z); d[3] = wm::__float_to_tf32(v.w);
    }
    if (tid < 128) { b1s[tid] = b1[tid]; W2s[tid] = W2[tid]; }
    const float b2 = b2p[0];
    __syncthreads();

    wm::fragment<wm::matrix_b, 16, 16, 8, wm::precision::tf32, wm::row_major> bfr[32];
    #pragma unroll
    for (int k = 0; k < 32; k++)
        wm::load_matrix_sync(bfr[k], &sm[(k * 8) * 132 + warp * 16], 132);
    __syncthreads();

    auto stage = [&](int tile, int b) {
        float* dst = As + b * 16896;
        const int r0 = tile << 6;
        #pragma unroll
        for (int i = tid; i < 4096; i += 256) {
            int r = i >> 6, c4 = i & 63;
            int g = r0 + r;
            int sz = (g < nA) ? 16 : 0;
            unsigned da = (unsigned)__cvta_generic_to_shared(&dst[r * 264 + c4 * 4]);
            asm volatile("cp.async.cg.shared.global [%0], [%1], 16, %2;\n"
                         :: "r"(da), "l"(A + (size_t)g * 256 + c4 * 4), "r"(sz));
        }
        asm volatile("cp.async.commit_group;\n");
    };

    const int ntiles = (nA + 63) >> 6;
    int t = blockIdx.x;
    if (t < ntiles) stage(t, 0);
    int buf = 0;
    for (; t < ntiles; t += gridDim.x) {
        int tn = t + gridDim.x;
        if (tn < ntiles) { stage(tn, buf ^ 1); asm volatile("cp.async.wait_group 1;\n"); }
        else             {                     asm volatile("cp.async.wait_group 0;\n"); }
        __syncthreads();

        float* Ab = As + buf * 16896;
        wm::fragment<wm::accumulator, 16, 16, 8, float> acc[4];
        #pragma unroll
        for (int m = 0; m < 4; m++) wm::fill_fragment(acc[m], 0.f);
        #pragma unroll
        for (int k = 0; k < 32; k++) {
            #pragma unroll
            for (int m = 0; m < 4; m++) {
                wm::fragment<wm::matrix_a, 16, 16, 8, wm::precision::tf32, wm::row_major> af;
                wm::load_matrix_sync(af, &Ab[(m * 16) * 264 + k * 8], 264);
                wm::mma_sync(acc[m], af, bfr[k], acc[m]);
            }
        }
        #pragma unroll
        for (int m = 0; m < 4; m++)
            wm::store_matrix_sync(&Hs[(m * 16) * 132 + warp * 16], acc[m], 132,
                                  wm::mem_row_major);
        __syncthreads();

        const int row0 = t << 6;
        #pragma unroll
        for (int r8 = 0; r8 < 8; r8++) {
            int r = warp * 8 + r8;
            int c = lane * 4;
            float4 h = *(const float4*)&Hs[r * 132 + c];
            float s = fast_tanh(h.x + b1s[c])     * W2s[c]
                    + fast_tanh(h.y + b1s[c + 1]) * W2s[c + 1]
                    + fast_tanh(h.z + b1s[c + 2]) * W2s[c + 2]
                    + fast_tanh(h.w + b1s[c + 3]) * W2s[c + 3];
            #pragma unroll
            for (int o = 16; o > 0; o >>= 1) s += __shfl_xor_sync(0xffffffffu, s, o);
            int g = row0 + r;
            if (lane == 0 && g < nA) g_exp[g] = fast_exp(s + b2);
        }
        buf ^= 1;
    }
}

// ---------------- denom + count ----------------------------------------------
__global__ void k_accum(const void* __restrict__ ti, int nA) {
    int a = blockIdx.x * blockDim.x + threadIdx.x;
    if (a >= nA) return;
    int t = team_of(ti, a, g_idxflag);
    atomicAdd(&g_denom[t], g_exp[a]);
    atomicAdd(&g_count[t], 1);
}

// ---------------- scan (counts -> offsets) -----------------------------------
__global__ void k_scan1(int nT) {
    __shared__ int ws[32];
    int i = blockIdx.x * 1024 + threadIdx.x;
    int lane = threadIdx.x & 31, wid = threadIdx.x >> 5;
    int v = (i < nT) ? g_count[i] : 0;
    int inc = v;
    #pragma unroll
    for (int o = 1; o < 32; o <<= 1) {
        int n = __shfl_up_sync(0xffffffffu, inc, o);
        if (lane >= o) inc += n;
    }
    if (lane == 31) ws[wid] = inc;
    __syncthreads();
    if (wid == 0) {
        int tt = ws[lane];
        #pragma unroll
        for (int o = 1; o < 32; o <<= 1) {
            int n = __shfl_up_sync(0xffffffffu, tt, o);
            if (lane >= o) tt += n;
        }
        ws[lane] = tt;
    }
    __syncthreads();
    int warpPre = wid ? ws[wid - 1] : 0;
    if (i < nT) g_offs[i] = warpPre + inc - v;
    if (threadIdx.x == 1023) g_bsum[blockIdx.x] = warpPre + inc;
}

__global__ void k_scan2(int nb) {
    if (threadIdx.x == 0 && blockIdx.x == 0) {
        int run = 0;
        for (int b = 0; b < nb; b++) { int t = g_bsum[b]; g_bsum[b] = run; run += t; }
    }
}

__global__ void k_scan3(int nT) {
    int i = blockIdx.x * blockDim.x + threadIdx.x;
    if (i < nT) g_offs[i] += g_bsum[i >> 10];
}

// ---------------- scatter: CSR pairs + attn output ---------------------------
__global__ void k_scatter(const void* __restrict__ ti, float* __restrict__ attn, int nA) {
    int a = blockIdx.x * blockDim.x + threadIdx.x;
    if (a >= nA) return;
    int t = team_of(ti, a, g_idxflag);
    float w = g_exp[a] / g_denom[t];
    attn[a] = w;
    int p = atomicAdd(&g_cursor[t], 1);
    g_pair[g_offs[t] + p] = make_int2(a, __float_as_int(w));
}

// ---------------- pool: warp per team -----------------------------------------
__global__ void k_pool(const float* __restrict__ A, int nT) {
    int t = (blockIdx.x * blockDim.x + threadIdx.x) >> 5;
    if (t >= nT) return;
    int lane = threadIdx.x & 31;
    int start = g_offs[t];
    int cnt   = g_count[t];
    float4 a0 = make_float4(0.f, 0.f, 0.f, 0.f);
    float4 a1 = make_float4(0.f, 0.f, 0.f, 0.f);
    for (int i = 0; i < cnt; i++) {
        int2 pr = g_pair[start + i];
        float w = __int_as_float(pr.y);
        const float4* row = (const float4*)A + (size_t)pr.x * 64;
        float4 v0 = __ldg(&row[lane * 2]);
        float4 v1 = __ldg(&row[lane * 2 + 1]);
        a0.x += w * v0.x; a0.y += w * v0.y; a0.z += w * v0.z; a0.w += w * v0.w;
        a1.x += w * v1.x; a1.y += w * v1.y; a1.z += w * v1.z; a1.w += w * v1.w;
    }
    float4* dst = (float4*)g_teamh + (size_t)t * 64;
    dst[lane * 2] = a0; dst[lane * 2 + 1] = a1;
}

// ---------------- GEMM3: out = relu(team_h @ Wo + bo) ------------------------
__global__ void __launch_bounds__(256, 1)
k_gemm3(const float* __restrict__ Wo, const float* __restrict__ bo,
        float* __restrict__ out, int nT)
{
    extern __shared__ float sm[];
    float* As  = sm;
    float* Hs  = sm + 33792;
    float* bos = Hs + 8448;
    const int tid = threadIdx.x, warp = tid >> 5, lane = tid & 31;
    const int color = blockIdx.x & 1;
    const int nOff = color << 7;

    for (int i = tid; i < 8192; i += 256) {
        int r = i >> 5, c4 = i & 31;
        float4 v = ((const float4*)Wo)[r * 64 + (nOff >> 2) + c4];
        float* d = &sm[r * 132 + c4 * 4];
        d[0] = wm::__float_to_tf32(v.x); d[1] = wm::__float_to_tf32(v.y);
        d[2] = wm::__float_to_tf32(v.z); d[3] = wm::__float_to_tf32(v.w);
    }
    if (tid < 128) bos[tid] = bo[nOff + tid];
    __syncthreads();

    wm::fragment<wm::matrix_b, 16, 16, 8, wm::precision::tf32, wm::row_major> bfr[32];
    #pragma unroll
    for (int k = 0; k < 32; k++)
        wm::load_matrix_sync(bfr[k], &sm[(k * 8) * 132 + warp * 16], 132);
    __syncthreads();

    const float* src = g_teamh;
    auto stage = [&](int tile, int b) {
        float* dst = As + b * 16896;
        const int r0 = tile << 6;
        #pragma unroll
        for (int i = tid; i < 4096; i += 256) {
            int r = i >> 6, c4 = i & 63;
            int g = r0 + r;
            int sz = (g < nT) ? 16 : 0;
            unsigned da = (unsigned)__cvta_generic_to_shared(&dst[r * 264 + c4 * 4]);
            asm volatile("cp.async.cg.shared.global [%0], [%1], 16, %2;\n"
                         :: "r"(da), "l"(src + (size_t)g * 256 + c4 * 4), "r"(sz));
        }
        asm volatile("cp.async.commit_group;\n");
    };

    const int ntiles = (nT + 63) >> 6;
    const int stride = gridDim.x >> 1;
    int t = blockIdx.x >> 1;
    if (t < ntiles) stage(t, 0);
    int buf = 0;
    for (; t < ntiles; t += stride) {
        int tn = t + stride;
        if (tn < ntiles) { stage(tn, buf ^ 1); asm volatile("cp.async.wait_group 1;\n"); }
        else             {                     asm volatile("cp.async.wait_group 0;\n"); }
        __syncthreads();

        float* Ab = As + buf * 16896;
        wm::fragment<wm::accumulator, 16, 16, 8, float> acc[4];
        #pragma unroll
        for (int m = 0; m < 4; m++) wm::fill_fragment(acc[m], 0.f);
        #pragma unroll
        for (int k = 0; k < 32; k++) {
            #pragma unroll
            for (int m = 0; m < 4; m++) {
                wm::fragment<wm::matrix_a, 16, 16, 8, wm::precision::tf32, wm::row_major> af;
                wm::load_matrix_sync(af, &Ab[(m * 16) * 264 + k * 8], 264);
                wm::mma_sync(acc[m], af, bfr[k], acc[m]);
            }
        }
        #pragma unroll
        for (int m = 0; m < 4; m++)
            wm::store_matrix_sync(&Hs[(m * 16) * 132 + warp * 16], acc[m], 132,
                                  wm::mem_row_major);
        __syncthreads();

        const int row0 = t << 6;
        #pragma unroll
        for (int r8 = 0; r8 < 8; r8++) {
            int r = warp * 8 + r8;
            int g = row0 + r;
            if (g < nT) {
                int c = lane * 4;
                float4 h = *(const float4*)&Hs[r * 132 + c];
                h.x = fmaxf(h.x + bos[c],     0.f);
                h.y = fmaxf(h.y + bos[c + 1], 0.f);
                h.z = fmaxf(h.z + bos[c + 2], 0.f);
                h.w = fmaxf(h.w + bos[c + 3], 0.f);
                *(float4*)&out[(size_t)g * 256 + nOff + c] = h;
            }
        }
        buf ^= 1;
    }
}

// ---------------- launch -------------------------------------------------------
extern "C" void kernel_launch(void* const* d_in, const int* in_sizes, int n_in,
                              void* d_out, int out_size)
{
    const float* agent_h  = (const float*)d_in[0];
    const void*  team_idx = d_in[1];
    int wbase = (in_sizes[2] == 256 * 128) ? 2 : 3;
    const float* W1 = (const float*)d_in[wbase + 0];
    const float* b1 = (const float*)d_in[wbase + 1];
    const float* W2 = (const float*)d_in[wbase + 2];
    const float* b2 = (const float*)d_in[wbase + 3];
    const float* Wo = (const float*)d_in[wbase + 4];
    const float* bo = (const float*)d_in[wbase + 5];

    const int nA = in_sizes[0] / 256;
    const int nT = (out_size - nA) / 256;
    float* out  = (float*)d_out;
    float* attn = out + (size_t)nT * 256;

    cudaFuncSetAttribute(k_gemm1, cudaFuncAttributeMaxDynamicSharedMemorySize, SM_BYTES);
    cudaFuncSetAttribute(k_gemm3, cudaFuncAttributeMaxDynamicSharedMemorySize, SM_BYTES);

    const int nb = (nT + 1023) / 1024;

    k_init<<<(nT + 255) / 256, 256>>>(team_idx, nA, nT);
    k_gemm1<<<152, 256, SM_BYTES>>>(agent_h, W1, b1, W2, b2, nA);
    k_accum<<<(nA + 255) / 256, 256>>>(team_idx, nA);
    k_scan1<<<nb, 1024>>>(nT);
    k_scan2<<<1, 32>>>(nb);
    k_scan3<<<(nT + 255) / 256, 256>>>(nT);
    k_scatter<<<(nA + 255) / 256, 256>>>(team_idx, attn, nA);
    k_pool<<<(nT + 7) / 8, 256>>>(agent_h, nT);
    k_gemm3<<<152, 256, SM_BYTES>>>(Wo, bo, out, nT);
}